// round 14
// baseline (speedup 1.0000x reference)
#include <cuda_runtime.h>
#include <cstdint>

// SimpleGNN: 3x CGConv + mean-pool + linear.
// R14: edge_k's measured binder was L1 (87.8%), 83% of wavefronts being the
// per-edge smem weight re-reads (32 LDS.128/edge). Fix: warp task =
// (edge, half); lane owns channel pair c=64h+2l so the K=16 weights fit in
// 32 ull registers (no spill, unlike 4ch/lane). v4-RED scatter kept via
// lane-pair shuffle epilogue (32 atomic lane-ops/edge, same as R2).
// GEMM: R13's 128x128 f32x2 version (measured win). edge_k stays launch #3.

#define NN 50000
#define EE 800000
#define CC 128
#define ZP 512

typedef unsigned long long ull;

__device__ __align__(16) float g_P[(size_t)NN * ZP];   // node projections
__device__ __align__(16) float g_hA[(size_t)NN * CC];
__device__ __align__(16) float g_hB[(size_t)NN * CC];
__device__ __align__(16) float g_msg[(size_t)NN * CC]; // aggregated messages
__device__ __align__(16) float g_B[ZP * CC];           // packed node-projection weights
__device__ float g_cs[CC];                 // column sums for pooling
__device__ int   g_idx64;                  // 1 if edge_idx is int64, 0 if int32

// ---- f32x2 helpers (sm_100+) ----------------------------------------------
__device__ __forceinline__ ull pack2(float a, float b) {
    ull r; asm("mov.b64 %0, {%1, %2};" : "=l"(r) : "f"(a), "f"(b)); return r;
}
__device__ __forceinline__ void unpack2(ull v, float& a, float& b) {
    asm("mov.b64 {%0, %1}, %2;" : "=f"(a), "=f"(b) : "l"(v));
}
__device__ __forceinline__ ull fma2(ull a, ull b, ull c) {
    ull d; asm("fma.rn.f32x2 %0, %1, %2, %3;" : "=l"(d) : "l"(a), "l"(b), "l"(c));
    return d;
}

// ---------------------------------------------------------------------------
// layer-0 msg zero + edge-index dtype detection fused (keeps edge_k at launch
// index 3 for ncu capture).
__global__ void zero_detect_k(float* __restrict__ p, int n4,
                              const long long* __restrict__ e64, int N) {
    if (blockIdx.x == 0 && threadIdx.x == 0) {
        int ok64 = 1;
        for (int i = 0; i < 64; i++) {
            long long v = e64[i];
            if (v < 0 || v >= N) { ok64 = 0; break; }
        }
        g_idx64 = ok64;
    }
    float4* q = (float4*)p;
    for (int i = blockIdx.x * blockDim.x + threadIdx.x; i < n4;
         i += gridDim.x * blockDim.x)
        q[i] = make_float4(0.f, 0.f, 0.f, 0.f);
}

__global__ void zero_k(float* __restrict__ p, int n4) {
    float4* q = (float4*)p;
    for (int i = blockIdx.x * blockDim.x + threadIdx.x; i < n4;
         i += gridDim.x * blockDim.x)
        q[i] = make_float4(0.f, 0.f, 0.f, 0.f);
}

// ---------------------------------------------------------------------------
// pack the 512x128 node-projection weight matrix:
// rows   0..127 : Wf[:,   0:128] (dst f) | 128..255 : Wf[:,128:256] (src f)
// rows 256..383 : Ws[:,   0:128] (dst s) | 384..511 : Ws[:,128:256] (src s)
__global__ void pack_B(const float* __restrict__ Wf, const float* __restrict__ Ws) {
    int j = blockIdx.x * blockDim.x + threadIdx.x;
    if (j >= ZP * CC) return;
    int row  = j >> 7;
    int k    = j & 127;
    int c    = row & 127;
    int part = row >> 7;
    const float* W = (part < 2) ? Wf : Ws;
    int off = (part & 1) ? 128 : 0;
    g_B[j] = W[c * 272 + off + k];
}

// ---------------------------------------------------------------------------
// P[M,512] = H[M,128] @ g_B^T. 128x128 tile, 256 threads, 8x8 per thread,
// f32x2 packed FMA (R13, measured win).
__global__ void gemm_k(const float* __restrict__ H, int M) {
    __shared__ float As[16][132];
    __shared__ float Bs[16][132];
    int tid = threadIdx.x;
    int tx = tid & 15, ty = tid >> 4;
    int i0 = blockIdx.x * 128, j0 = blockIdx.y * 128;

    ull acc2[8][4];
#pragma unroll
    for (int r = 0; r < 8; r++)
#pragma unroll
        for (int p = 0; p < 4; p++) acc2[r][p] = 0ull;

    for (int k0 = 0; k0 < 128; k0 += 16) {
#pragma unroll
        for (int rep = 0; rep < 2; rep++) {
            int v   = tid + rep * 256;    // 0..511
            int row = v & 127;
            int kq  = v >> 7;             // 0..3
            float4 va = make_float4(0.f, 0.f, 0.f, 0.f);
            if (i0 + row < M)
                va = *(const float4*)(H + (size_t)(i0 + row) * 128 + k0 + kq * 4);
            As[kq * 4 + 0][row] = va.x; As[kq * 4 + 1][row] = va.y;
            As[kq * 4 + 2][row] = va.z; As[kq * 4 + 3][row] = va.w;
            float4 vb = *(const float4*)(g_B + (size_t)(j0 + row) * 128 + k0 + kq * 4);
            Bs[kq * 4 + 0][row] = vb.x; Bs[kq * 4 + 1][row] = vb.y;
            Bs[kq * 4 + 2][row] = vb.z; Bs[kq * 4 + 3][row] = vb.w;
        }
        __syncthreads();
#pragma unroll
        for (int kk = 0; kk < 16; kk++) {
            float4 a0 = *(const float4*)&As[kk][ty * 8];
            float4 a1 = *(const float4*)&As[kk][ty * 8 + 4];
            ull b0 = *(const ull*)&Bs[kk][tx * 8 + 0];
            ull b1 = *(const ull*)&Bs[kk][tx * 8 + 2];
            ull b2 = *(const ull*)&Bs[kk][tx * 8 + 4];
            ull b3 = *(const ull*)&Bs[kk][tx * 8 + 6];
            float a[8] = {a0.x, a0.y, a0.z, a0.w, a1.x, a1.y, a1.z, a1.w};
#pragma unroll
            for (int r = 0; r < 8; r++) {
                ull pa = pack2(a[r], a[r]);
                acc2[r][0] = fma2(pa, b0, acc2[r][0]);
                acc2[r][1] = fma2(pa, b1, acc2[r][1]);
                acc2[r][2] = fma2(pa, b2, acc2[r][2]);
                acc2[r][3] = fma2(pa, b3, acc2[r][3]);
            }
        }
        __syncthreads();
    }

#pragma unroll
    for (int r = 0; r < 8; r++) {
        int row = i0 + ty * 8 + r;
        if (row < M) {
            float o[8];
            unpack2(acc2[r][0], o[0], o[1]);
            unpack2(acc2[r][1], o[2], o[3]);
            unpack2(acc2[r][2], o[4], o[5]);
            unpack2(acc2[r][3], o[6], o[7]);
            float* dst = g_P + (size_t)row * ZP + j0 + tx * 8;
            *(float4*)(dst + 0) = make_float4(o[0], o[1], o[2], o[3]);
            *(float4*)(dst + 4) = make_float4(o[4], o[5], o[6], o[7]);
        }
    }
}

// ---------------------------------------------------------------------------
__device__ __forceinline__ float sigm(float x) {
    return __fdividef(1.f, 1.f + __expf(-x));
}
__device__ __forceinline__ float sftp(float x) {
    return fmaxf(x, 0.f) + __logf(1.f + __expf(-fabsf(x)));
}

// ---------------------------------------------------------------------------
// Warp task = (edge, half). Lane owns channel pair c = 64h + 2*lane.
// Weights: 32 ull regs (16 k x channel-pair x 2 gates), loaded once per warp.
// Per edge: idx + 4 broadcast ew LDG + 4 coalesced 256B P-gathers + 16 packs +
// 32 FFMA2 + activation + shuffle-pair + red.global.add.v4.f32 (even lanes).
__global__ void edge_k(const void* __restrict__ eidx_raw,
                       const float* __restrict__ ew,
                       const float* __restrict__ Wf, const float* __restrict__ Ws,
                       const float* __restrict__ bf, const float* __restrict__ bs,
                       int E) {
    int tid  = threadIdx.x;
    int lane = tid & 31;
    int wg   = blockIdx.x * (blockDim.x >> 5) + (tid >> 5);
    int nwg  = gridDim.x * (blockDim.x >> 5);   // even by construction
    int h    = wg & 1;
    int c    = h * 64 + lane * 2;               // this lane's channel pair

    // register-resident K-weights, channel-paired: wf2[k] = (Wf[c][256+k], Wf[c+1][256+k])
    ull wf2[16], ws2[16];
#pragma unroll
    for (int k = 0; k < 16; k++) {
        wf2[k] = pack2(__ldg(Wf + (size_t)c * 272 + 256 + k),
                       __ldg(Wf + (size_t)(c + 1) * 272 + 256 + k));
        ws2[k] = pack2(__ldg(Ws + (size_t)c * 272 + 256 + k),
                       __ldg(Ws + (size_t)(c + 1) * 272 + 256 + k));
    }
    float bf0 = __ldg(bf + c), bf1 = __ldg(bf + c + 1);
    float bs0 = __ldg(bs + c), bs1 = __ldg(bs + c + 1);

    const int is64 = g_idx64;
    const long long* e64 = (const long long*)eidx_raw;
    const int*       e32 = (const int*)eidx_raw;

    for (int e = wg >> 1; e < E; e += nwg >> 1) {
        int s, d;
        if (is64) {
            s = (int)__ldg(e64 + e);
            d = (int)__ldg(e64 + E + e);
        } else {
            s = __ldg(e32 + e);
            d = __ldg(e32 + E + e);
        }

        const float4* ewp = (const float4*)(ew + (size_t)e * 16);
        float4 w0 = __ldg(ewp + 0), w1 = __ldg(ewp + 1);
        float4 w2 = __ldg(ewp + 2), w3 = __ldg(ewp + 3);
        float ev[16] = {w0.x, w0.y, w0.z, w0.w, w1.x, w1.y, w1.z, w1.w,
                        w2.x, w2.y, w2.z, w2.w, w3.x, w3.y, w3.z, w3.w};

        const float* Pd = g_P + (size_t)d * ZP;
        const float* Ps = g_P + (size_t)s * ZP;
        float2 fd = *(const float2*)(Pd + c);          // warp: 256B coalesced
        float2 fs = *(const float2*)(Ps + 128 + c);
        float2 sd = *(const float2*)(Pd + 256 + c);
        float2 ss = *(const float2*)(Ps + 384 + c);

        ull FF = pack2(fd.x + fs.x + bf0, fd.y + fs.y + bf1);
        ull SS = pack2(sd.x + ss.x + bs0, sd.y + ss.y + bs1);

#pragma unroll
        for (int k = 0; k < 16; k++) {
            ull wvv = pack2(ev[k], ev[k]);
            FF = fma2(wvv, wf2[k], FF);
            SS = fma2(wvv, ws2[k], SS);
        }

        float f0, f1, s0, s1;
        unpack2(FF, f0, f1);
        unpack2(SS, s0, s1);
        float m0 = sigm(f0) * sftp(s0);
        float m1 = sigm(f1) * sftp(s1);

        // lane-pair combine: even lane issues v4 RED for channels [c, c+4)
        float m2 = __shfl_down_sync(0xffffffffu, m0, 1);
        float m3 = __shfl_down_sync(0xffffffffu, m1, 1);
        if (!(lane & 1)) {
            float* outp = g_msg + (size_t)d * CC + c;   // c = 64h+4i, 16B aligned
            asm volatile("red.global.add.v4.f32 [%0], {%1,%2,%3,%4};"
                         :: "l"(outp), "f"(m0), "f"(m1), "f"(m2), "f"(m3)
                         : "memory");
        }
    }
}

// ---------------------------------------------------------------------------
__global__ void combine_k(const float* __restrict__ h, float* __restrict__ o,
                          int n4, int relu) {
    const float4* h4 = (const float4*)h;
    const float4* m4 = (const float4*)g_msg;
    float4* o4 = (float4*)o;
    for (int i = blockIdx.x * blockDim.x + threadIdx.x; i < n4;
         i += gridDim.x * blockDim.x) {
        float4 a = h4[i], b = m4[i];
        a.x += b.x; a.y += b.y; a.z += b.z; a.w += b.w;
        if (relu) {
            a.x = fmaxf(a.x, 0.f); a.y = fmaxf(a.y, 0.f);
            a.z = fmaxf(a.z, 0.f); a.w = fmaxf(a.w, 0.f);
        }
        o4[i] = a;
    }
}

// ---------------------------------------------------------------------------
__global__ void colsum_k(const float* __restrict__ h, int M) {
    int c = threadIdx.x;   // 128 threads
    float loc = 0.f;
    for (int i = blockIdx.x; i < M; i += gridDim.x)
        loc += h[(size_t)i * CC + c];
    atomicAdd(&g_cs[c], loc);
}

__global__ void final_k(const float* __restrict__ Wlin,
                        const float* __restrict__ blin,
                        float* __restrict__ out, float invM) {
    int o = threadIdx.x;
    if (o < 64) {
        float a = 0.f;
#pragma unroll 4
        for (int c = 0; c < 128; c++) a += g_cs[c] * Wlin[o * 128 + c];
        out[o] = blin[o] + a * invM;
    }
}

// ---------------------------------------------------------------------------
extern "C" void kernel_launch(void* const* d_in, const int* in_sizes, int n_in,
                              void* d_out, int out_size) {
    const float* x    = (const float*)d_in[0];
    const void*  eidx = d_in[1];
    const float* ew   = (const float*)d_in[2];
    const float* Wf[3] = {(const float*)d_in[3], (const float*)d_in[7],  (const float*)d_in[11]};
    const float* bf[3] = {(const float*)d_in[4], (const float*)d_in[8],  (const float*)d_in[12]};
    const float* Ws[3] = {(const float*)d_in[5], (const float*)d_in[9],  (const float*)d_in[13]};
    const float* bs[3] = {(const float*)d_in[6], (const float*)d_in[10], (const float*)d_in[14]};
    const float* Wlin = (const float*)d_in[15];
    const float* blin = (const float*)d_in[16];
    float* out = (float*)d_out;

    int M = in_sizes[0] / 128;   // 50000
    int E = in_sizes[2] / 16;    // 800000

    float *hA, *hB, *msg, *cs;
    cudaGetSymbolAddress((void**)&hA,  g_hA);
    cudaGetSymbolAddress((void**)&hB,  g_hB);
    cudaGetSymbolAddress((void**)&msg, g_msg);
    cudaGetSymbolAddress((void**)&cs,  g_cs);

    const float* hin[3]  = {x, hA, hB};
    float*       hout[3] = {hA, hB, hA};

    dim3 ggrid((M + 127) / 128, ZP / 128);
    int n4 = M * CC / 4;

    // ---- layer 0, ordered so edge_k is launch index 3 (ncu capture) ----
    zero_detect_k<<<1024, 256>>>(msg, n4, (const long long*)eidx, M);   // 0
    pack_B<<<(ZP * CC + 255) / 256, 256>>>(Wf[0], Ws[0]);               // 1
    gemm_k<<<ggrid, 256>>>(x, M);                                       // 2
    edge_k<<<2368, 256>>>(eidx, ew, Wf[0], Ws[0], bf[0], bs[0], E);     // 3
    combine_k<<<1024, 256>>>(x, hA, n4, 1);                             // 4

    // ---- layers 1, 2 ----
    for (int l = 1; l < 3; l++) {
        pack_B<<<(ZP * CC + 255) / 256, 256>>>(Wf[l], Ws[l]);
        gemm_k<<<ggrid, 256>>>(hin[l], M);
        zero_k<<<1024, 256>>>(msg, n4);
        edge_k<<<2368, 256>>>(eidx, ew, Wf[l], Ws[l], bf[l], bs[l], E);
        combine_k<<<1024, 256>>>(hin[l], hout[l], n4, (l < 2) ? 1 : 0);
    }

    // ---- mean pool + linear ----
    zero_k<<<1, 32>>>(cs, CC / 4);
    colsum_k<<<512, 128>>>(hA, M);
    final_k<<<1, 64>>>(Wlin, blin, out, 1.0f / (float)M);
}

// round 17
// speedup vs baseline: 2.0022x; 2.0022x over previous
#include <cuda_runtime.h>
#include <cstdint>

// SimpleGNN: 3x CGConv + mean-pool + linear.
// R17: same hypothesis as R15 (R13 profile: L1 87.8%, 83% of wavefronts are
// per-edge smem weight re-reads -> share each weight LDS.128 across TWO edges,
// halving weight wavefronts to 64/edge) but implemented with plain float4 +
// fmaf (fma pipe was only 24.4% in R13; doubling FFMA stays under the L1
// bound) instead of the f32x2 asm that coincided with 2x infra failures.
// GEMM: R13's 128x128 f32x2 version (measured win). edge_k stays launch #3.

#define NN 50000
#define EE 800000
#define CC 128
#define ZP 512

typedef unsigned long long ull;

__device__ __align__(16) float g_P[(size_t)NN * ZP];   // node projections
__device__ __align__(16) float g_hA[(size_t)NN * CC];
__device__ __align__(16) float g_hB[(size_t)NN * CC];
__device__ __align__(16) float g_msg[(size_t)NN * CC]; // aggregated messages
__device__ __align__(16) float g_B[ZP * CC];           // packed node-projection weights
__device__ float g_cs[CC];                 // column sums for pooling
__device__ int   g_idx64;                  // 1 if edge_idx is int64, 0 if int32

// ---- f32x2 helpers (used only in gemm_k, which is proven stable) -----------
__device__ __forceinline__ ull pack2(float a, float b) {
    ull r; asm("mov.b64 %0, {%1, %2};" : "=l"(r) : "f"(a), "f"(b)); return r;
}
__device__ __forceinline__ void unpack2(ull v, float& a, float& b) {
    asm("mov.b64 {%0, %1}, %2;" : "=f"(a), "=f"(b) : "l"(v));
}
__device__ __forceinline__ ull fma2(ull a, ull b, ull c) {
    ull d; asm("fma.rn.f32x2 %0, %1, %2, %3;" : "=l"(d) : "l"(a), "l"(b), "l"(c));
    return d;
}

// ---------------------------------------------------------------------------
// layer-0 msg zero + edge-index dtype detection fused (keeps edge_k at launch
// index 3 for ncu capture).
__global__ void zero_detect_k(float* __restrict__ p, int n4,
                              const long long* __restrict__ e64, int N) {
    if (blockIdx.x == 0 && threadIdx.x == 0) {
        int ok64 = 1;
        for (int i = 0; i < 64; i++) {
            long long v = e64[i];
            if (v < 0 || v >= N) { ok64 = 0; break; }
        }
        g_idx64 = ok64;
    }
    float4* q = (float4*)p;
    for (int i = blockIdx.x * blockDim.x + threadIdx.x; i < n4;
         i += gridDim.x * blockDim.x)
        q[i] = make_float4(0.f, 0.f, 0.f, 0.f);
}

__global__ void zero_k(float* __restrict__ p, int n4) {
    float4* q = (float4*)p;
    for (int i = blockIdx.x * blockDim.x + threadIdx.x; i < n4;
         i += gridDim.x * blockDim.x)
        q[i] = make_float4(0.f, 0.f, 0.f, 0.f);
}

// ---------------------------------------------------------------------------
// pack the 512x128 node-projection weight matrix
__global__ void pack_B(const float* __restrict__ Wf, const float* __restrict__ Ws) {
    int j = blockIdx.x * blockDim.x + threadIdx.x;
    if (j >= ZP * CC) return;
    int row  = j >> 7;
    int k    = j & 127;
    int c    = row & 127;
    int part = row >> 7;
    const float* W = (part < 2) ? Wf : Ws;
    int off = (part & 1) ? 128 : 0;
    g_B[j] = W[c * 272 + off + k];
}

// ---------------------------------------------------------------------------
// P[M,512] = H[M,128] @ g_B^T. 128x128 tile, 256 threads, 8x8 per thread,
// f32x2 packed FMA (R13, measured win).
__global__ void gemm_k(const float* __restrict__ H, int M) {
    __shared__ float As[16][132];
    __shared__ float Bs[16][132];
    int tid = threadIdx.x;
    int tx = tid & 15, ty = tid >> 4;
    int i0 = blockIdx.x * 128, j0 = blockIdx.y * 128;

    ull acc2[8][4];
#pragma unroll
    for (int r = 0; r < 8; r++)
#pragma unroll
        for (int p = 0; p < 4; p++) acc2[r][p] = 0ull;

    for (int k0 = 0; k0 < 128; k0 += 16) {
#pragma unroll
        for (int rep = 0; rep < 2; rep++) {
            int v   = tid + rep * 256;    // 0..511
            int row = v & 127;
            int kq  = v >> 7;             // 0..3
            float4 va = make_float4(0.f, 0.f, 0.f, 0.f);
            if (i0 + row < M)
                va = *(const float4*)(H + (size_t)(i0 + row) * 128 + k0 + kq * 4);
            As[kq * 4 + 0][row] = va.x; As[kq * 4 + 1][row] = va.y;
            As[kq * 4 + 2][row] = va.z; As[kq * 4 + 3][row] = va.w;
            float4 vb = *(const float4*)(g_B + (size_t)(j0 + row) * 128 + k0 + kq * 4);
            Bs[kq * 4 + 0][row] = vb.x; Bs[kq * 4 + 1][row] = vb.y;
            Bs[kq * 4 + 2][row] = vb.z; Bs[kq * 4 + 3][row] = vb.w;
        }
        __syncthreads();
#pragma unroll
        for (int kk = 0; kk < 16; kk++) {
            float4 a0 = *(const float4*)&As[kk][ty * 8];
            float4 a1 = *(const float4*)&As[kk][ty * 8 + 4];
            ull b0 = *(const ull*)&Bs[kk][tx * 8 + 0];
            ull b1 = *(const ull*)&Bs[kk][tx * 8 + 2];
            ull b2 = *(const ull*)&Bs[kk][tx * 8 + 4];
            ull b3 = *(const ull*)&Bs[kk][tx * 8 + 6];
            float a[8] = {a0.x, a0.y, a0.z, a0.w, a1.x, a1.y, a1.z, a1.w};
#pragma unroll
            for (int r = 0; r < 8; r++) {
                ull pa = pack2(a[r], a[r]);
                acc2[r][0] = fma2(pa, b0, acc2[r][0]);
                acc2[r][1] = fma2(pa, b1, acc2[r][1]);
                acc2[r][2] = fma2(pa, b2, acc2[r][2]);
                acc2[r][3] = fma2(pa, b3, acc2[r][3]);
            }
        }
        __syncthreads();
    }

#pragma unroll
    for (int r = 0; r < 8; r++) {
        int row = i0 + ty * 8 + r;
        if (row < M) {
            float o[8];
            unpack2(acc2[r][0], o[0], o[1]);
            unpack2(acc2[r][1], o[2], o[3]);
            unpack2(acc2[r][2], o[4], o[5]);
            unpack2(acc2[r][3], o[6], o[7]);
            float* dst = g_P + (size_t)row * ZP + j0 + tx * 8;
            *(float4*)(dst + 0) = make_float4(o[0], o[1], o[2], o[3]);
            *(float4*)(dst + 4) = make_float4(o[4], o[5], o[6], o[7]);
        }
    }
}

// ---------------------------------------------------------------------------
__device__ __forceinline__ float sigm(float x) {
    return __fdividef(1.f, 1.f + __expf(-x));
}
__device__ __forceinline__ float sftp(float x) {
    return fmaxf(x, 0.f) + __logf(1.f + __expf(-fabsf(x)));
}

// ---------------------------------------------------------------------------
// One warp processes TWO edges per iteration; lane owns channels 4l..4l+3.
// The k-loop loads each weight float4 ONCE and applies it to both edges, so
// weight LDS wavefronts drop from 128/edge (R13) to 64/edge. Plain fmaf math.
__global__ void edge_k(const void* __restrict__ eidx_raw,
                       const float* __restrict__ ew,
                       const float* __restrict__ Wf, const float* __restrict__ Ws,
                       const float* __restrict__ bf, const float* __restrict__ bs,
                       int E) {
    __shared__ float4 wfe[16][32];   // [k][lane] = Wf[4l..4l+3][256+k]
    __shared__ float4 wse[16][32];
    __shared__ float4 bfv[32], bsv[32];
    int tid = threadIdx.x;
    for (int idx = tid; idx < 512; idx += blockDim.x) {
        int k = idx >> 5, l = idx & 31, c0 = l << 2;
        wfe[k][l] = make_float4(Wf[(c0 + 0) * 272 + 256 + k],
                                Wf[(c0 + 1) * 272 + 256 + k],
                                Wf[(c0 + 2) * 272 + 256 + k],
                                Wf[(c0 + 3) * 272 + 256 + k]);
        wse[k][l] = make_float4(Ws[(c0 + 0) * 272 + 256 + k],
                                Ws[(c0 + 1) * 272 + 256 + k],
                                Ws[(c0 + 2) * 272 + 256 + k],
                                Ws[(c0 + 3) * 272 + 256 + k]);
    }
    if (tid < 32) {
        bfv[tid] = *(const float4*)(bf + tid * 4);
        bsv[tid] = *(const float4*)(bs + tid * 4);
    }
    __syncthreads();

    const int is64 = g_idx64;
    const long long* e64 = (const long long*)eidx_raw;
    const int*       e32 = (const int*)eidx_raw;

    int lane = tid & 31;
    int warp = blockIdx.x * (blockDim.x >> 5) + (tid >> 5);
    int nw   = gridDim.x * (blockDim.x >> 5);
    float4 bF = bfv[lane], bS = bsv[lane];
    int c0 = lane * 4;

    for (int i = warp; 2 * i < E; i += nw) {
        int ea = 2 * i;
        int eb = ea + 1;
        bool doB = (eb < E);
        int ebc = doB ? eb : ea;   // clamp (loads safe; edge-B RED predicated)

        int sa, da, sb, db;
        if (is64) {
            sa = (int)__ldg(e64 + ea);   da = (int)__ldg(e64 + E + ea);
            sb = (int)__ldg(e64 + ebc);  db = (int)__ldg(e64 + E + ebc);
        } else {
            sa = __ldg(e32 + ea);        da = __ldg(e32 + E + ea);
            sb = __ldg(e32 + ebc);       db = __ldg(e32 + E + ebc);
        }

        const float4* ewa = (const float4*)(ew + (size_t)ea * 16);
        const float4* ewb = (const float4*)(ew + (size_t)ebc * 16);
        float4 a0 = __ldg(ewa + 0), a1 = __ldg(ewa + 1),
               a2 = __ldg(ewa + 2), a3 = __ldg(ewa + 3);
        float4 b0 = __ldg(ewb + 0), b1 = __ldg(ewb + 1),
               b2 = __ldg(ewb + 2), b3 = __ldg(ewb + 3);
        float eva[16] = {a0.x, a0.y, a0.z, a0.w, a1.x, a1.y, a1.z, a1.w,
                         a2.x, a2.y, a2.z, a2.w, a3.x, a3.y, a3.z, a3.w};
        float evb[16] = {b0.x, b0.y, b0.z, b0.w, b1.x, b1.y, b1.z, b1.w,
                         b2.x, b2.y, b2.z, b2.w, b3.x, b3.y, b3.z, b3.w};

        const float* Pda = g_P + (size_t)da * ZP;
        const float* Psa = g_P + (size_t)sa * ZP;
        const float* Pdb = g_P + (size_t)db * ZP;
        const float* Psb = g_P + (size_t)sb * ZP;
        float4 fda = *(const float4*)(Pda + c0);
        float4 fsa = *(const float4*)(Psa + 128 + c0);
        float4 sda = *(const float4*)(Pda + 256 + c0);
        float4 ssa = *(const float4*)(Psa + 384 + c0);
        float4 fdb = *(const float4*)(Pdb + c0);
        float4 fsb = *(const float4*)(Psb + 128 + c0);
        float4 sdb = *(const float4*)(Pdb + 256 + c0);
        float4 ssb = *(const float4*)(Psb + 384 + c0);

        float4 FA, SA, FB, SB;
        FA.x = fda.x + fsa.x + bF.x; FA.y = fda.y + fsa.y + bF.y;
        FA.z = fda.z + fsa.z + bF.z; FA.w = fda.w + fsa.w + bF.w;
        SA.x = sda.x + ssa.x + bS.x; SA.y = sda.y + ssa.y + bS.y;
        SA.z = sda.z + ssa.z + bS.z; SA.w = sda.w + ssa.w + bS.w;
        FB.x = fdb.x + fsb.x + bF.x; FB.y = fdb.y + fsb.y + bF.y;
        FB.z = fdb.z + fsb.z + bF.z; FB.w = fdb.w + fsb.w + bF.w;
        SB.x = sdb.x + ssb.x + bS.x; SB.y = sdb.y + ssb.y + bS.y;
        SB.z = sdb.z + ssb.z + bS.z; SB.w = sdb.w + ssb.w + bS.w;

#pragma unroll
        for (int k = 0; k < 16; k++) {
            float4 wfv = wfe[k][lane];   // 1 LDS.128, shared by both edges
            float4 wsv = wse[k][lane];   // 1 LDS.128
            float wa = eva[k], wb = evb[k];
            FA.x = fmaf(wa, wfv.x, FA.x); FA.y = fmaf(wa, wfv.y, FA.y);
            FA.z = fmaf(wa, wfv.z, FA.z); FA.w = fmaf(wa, wfv.w, FA.w);
            FB.x = fmaf(wb, wfv.x, FB.x); FB.y = fmaf(wb, wfv.y, FB.y);
            FB.z = fmaf(wb, wfv.z, FB.z); FB.w = fmaf(wb, wfv.w, FB.w);
            SA.x = fmaf(wa, wsv.x, SA.x); SA.y = fmaf(wa, wsv.y, SA.y);
            SA.z = fmaf(wa, wsv.z, SA.z); SA.w = fmaf(wa, wsv.w, SA.w);
            SB.x = fmaf(wb, wsv.x, SB.x); SB.y = fmaf(wb, wsv.y, SB.y);
            SB.z = fmaf(wb, wsv.z, SB.z); SB.w = fmaf(wb, wsv.w, SB.w);
        }

        float4 ma;
        ma.x = sigm(FA.x) * sftp(SA.x);
        ma.y = sigm(FA.y) * sftp(SA.y);
        ma.z = sigm(FA.z) * sftp(SA.z);
        ma.w = sigm(FA.w) * sftp(SA.w);
        float* outa = g_msg + (size_t)da * CC + c0;
        asm volatile("red.global.add.v4.f32 [%0], {%1,%2,%3,%4};"
                     :: "l"(outa), "f"(ma.x), "f"(ma.y), "f"(ma.z), "f"(ma.w)
                     : "memory");

        if (doB) {
            float4 mb;
            mb.x = sigm(FB.x) * sftp(SB.x);
            mb.y = sigm(FB.y) * sftp(SB.y);
            mb.z = sigm(FB.z) * sftp(SB.z);
            mb.w = sigm(FB.w) * sftp(SB.w);
            float* outb = g_msg + (size_t)db * CC + c0;
            asm volatile("red.global.add.v4.f32 [%0], {%1,%2,%3,%4};"
                         :: "l"(outb), "f"(mb.x), "f"(mb.y), "f"(mb.z), "f"(mb.w)
                         : "memory");
        }
    }
}

// ---------------------------------------------------------------------------
__global__ void combine_k(const float* __restrict__ h, float* __restrict__ o,
                          int n4, int relu) {
    const float4* h4 = (const float4*)h;
    const float4* m4 = (const float4*)g_msg;
    float4* o4 = (float4*)o;
    for (int i = blockIdx.x * blockDim.x + threadIdx.x; i < n4;
         i += gridDim.x * blockDim.x) {
        float4 a = h4[i], b = m4[i];
        a.x += b.x; a.y += b.y; a.z += b.z; a.w += b.w;
        if (relu) {
            a.x = fmaxf(a.x, 0.f); a.y = fmaxf(a.y, 0.f);
            a.z = fmaxf(a.z, 0.f); a.w = fmaxf(a.w, 0.f);
        }
        o4[i] = a;
    }
}

// ---------------------------------------------------------------------------
__global__ void colsum_k(const float* __restrict__ h, int M) {
    int c = threadIdx.x;   // 128 threads
    float loc = 0.f;
    for (int i = blockIdx.x; i < M; i += gridDim.x)
        loc += h[(size_t)i * CC + c];
    atomicAdd(&g_cs[c], loc);
}

__global__ void final_k(const float* __restrict__ Wlin,
                        const float* __restrict__ blin,
                        float* __restrict__ out, float invM) {
    int o = threadIdx.x;
    if (o < 64) {
        float a = 0.f;
#pragma unroll 4
        for (int c = 0; c < 128; c++) a += g_cs[c] * Wlin[o * 128 + c];
        out[o] = blin[o] + a * invM;
    }
}

// ---------------------------------------------------------------------------
extern "C" void kernel_launch(void* const* d_in, const int* in_sizes, int n_in,
                              void* d_out, int out_size) {
    const float* x    = (const float*)d_in[0];
    const void*  eidx = d_in[1];
    const float* ew   = (const float*)d_in[2];
    const float* Wf[3] = {(const float*)d_in[3], (const float*)d_in[7],  (const float*)d_in[11]};
    const float* bf[3] = {(const float*)d_in[4], (const float*)d_in[8],  (const float*)d_in[12]};
    const float* Ws[3] = {(const float*)d_in[5], (const float*)d_in[9],  (const float*)d_in[13]};
    const float* bs[3] = {(const float*)d_in[6], (const float*)d_in[10], (const float*)d_in[14]};
    const float* Wlin = (const float*)d_in[15];
    const float* blin = (const float*)d_in[16];
    float* out = (float*)d_out;

    int M = in_sizes[0] / 128;   // 50000
    int E = in_sizes[2] / 16;    // 800000

    float *hA, *hB, *msg, *cs;
    cudaGetSymbolAddress((void**)&hA,  g_hA);
    cudaGetSymbolAddress((void**)&hB,  g_hB);
    cudaGetSymbolAddress((void**)&msg, g_msg);
    cudaGetSymbolAddress((void**)&cs,  g_cs);

    const float* hin[3]  = {x, hA, hB};
    float*       hout[3] = {hA, hB, hA};

    dim3 ggrid((M + 127) / 128, ZP / 128);
    int n4 = M * CC / 4;

    // ---- layer 0, ordered so edge_k is launch index 3 (ncu capture) ----
    zero_detect_k<<<1024, 256>>>(msg, n4, (const long long*)eidx, M);   // 0
    pack_B<<<(ZP * CC + 255) / 256, 256>>>(Wf[0], Ws[0]);               // 1
    gemm_k<<<ggrid, 256>>>(x, M);                                       // 2
    edge_k<<<1184, 256>>>(eidx, ew, Wf[0], Ws[0], bf[0], bs[0], E);     // 3
    combine_k<<<1024, 256>>>(x, hA, n4, 1);                             // 4

    // ---- layers 1, 2 ----
    for (int l = 1; l < 3; l++) {
        pack_B<<<(ZP * CC + 255) / 256, 256>>>(Wf[l], Ws[l]);
        gemm_k<<<ggrid, 256>>>(hin[l], M);
        zero_k<<<1024, 256>>>(msg, n4);
        edge_k<<<1184, 256>>>(eidx, ew, Wf[l], Ws[l], bf[l], bs[l], E);
        combine_k<<<1024, 256>>>(hin[l], hout[l], n4, (l < 2) ? 1 : 0);
    }

    // ---- mean pool + linear ----
    zero_k<<<1, 32>>>(cs, CC / 4);
    colsum_k<<<512, 128>>>(hA, M);
    final_k<<<1, 64>>>(Wlin, blin, out, 1.0f / (float)M);
}